// round 15
// baseline (speedup 1.0000x reference)
#include <cuda_runtime.h>
#include <cuda_fp16.h>
#include <cstdint>
#include <math.h>

// ---------------------------------------------------------------- constants
#define N_PIX     8192
#define N_TOK     8
#define DIM       512
#define INNER     512
#define INNER3    1536
#define SCALE_F   0.125f
#define M_ROWS    65536

// GEMM tiling (fp16 m16n8k16) — exact R10/R14 configuration
#define BM     128
#define BN     128
#define BK     32
#define STAGES 4
#define TK     (DIM / BK)               // 16 K-tiles
#define ROWB   80
#define TILE_BYTES  (128 * ROWB)        // 10240
#define STAGE_BYTES (2 * TILE_BYTES)    // 20480
#define GEMM_SMEM   (STAGES * STAGE_BYTES)  // 81920

#define QPH    520                      // attn smem pitch in halves

// Scratch (__device__ globals per allocation rules)
__device__ __half g_qkv[(size_t)M_ROWS * INNER3];
__device__ __half g_att[(size_t)M_ROWS * INNER];
__device__ __half g_xtf[(size_t)M_ROWS * DIM];
__device__ __half g_wqkvT[(size_t)INNER3 * DIM];
__device__ __half g_woutT[(size_t)INNER * DIM];

// ---------------------------------------------------------------- helpers
__device__ __forceinline__ uint32_t smem_u32(const void* p) {
    uint32_t a;
    asm("{ .reg .u64 t; cvta.to.shared.u64 t, %1; cvt.u32.u64 %0, t; }"
        : "=r"(a) : "l"(p));
    return a;
}
__device__ __forceinline__ void cp16(uint32_t dst, const void* src) {
    asm volatile("cp.async.cg.shared.global [%0], [%1], 16;"
                 :: "r"(dst), "l"(src));
}
__device__ __forceinline__ void cp_commit() {
    asm volatile("cp.async.commit_group;" ::: "memory");
}
template <int N> __device__ __forceinline__ void cp_wait() {
    asm volatile("cp.async.wait_group %0;" :: "n"(N) : "memory");
}
__device__ __forceinline__ void ldmx4(uint32_t* r, uint32_t addr) {
    asm volatile("ldmatrix.sync.aligned.m8n8.x4.shared.b16 {%0,%1,%2,%3}, [%4];"
                 : "=r"(r[0]), "=r"(r[1]), "=r"(r[2]), "=r"(r[3]) : "r"(addr));
}
__device__ __forceinline__ void mma_f16(float* c, uint32_t a0, uint32_t a1,
                                        uint32_t a2, uint32_t a3,
                                        uint32_t b0, uint32_t b1) {
    asm volatile(
        "mma.sync.aligned.m16n8k16.row.col.f32.f16.f16.f32 "
        "{%0,%1,%2,%3}, {%4,%5,%6,%7}, {%8,%9}, {%0,%1,%2,%3};"
        : "+f"(c[0]), "+f"(c[1]), "+f"(c[2]), "+f"(c[3])
        : "r"(a0), "r"(a1), "r"(a2), "r"(a3), "r"(b0), "r"(b1));
}
__device__ __forceinline__ uint32_t packh2(float x, float y) {
    __half2 h = __floats2half2_rn(x, y);
    return *reinterpret_cast<uint32_t*>(&h);
}

// packed f32x2 ops (Blackwell base ISA)
__device__ __forceinline__ unsigned long long pkf2(float x, float y) {
    unsigned long long r;
    asm("mov.b64 %0, {%1, %2};" : "=l"(r) : "f"(x), "f"(y));
    return r;
}
__device__ __forceinline__ void upkf2(unsigned long long v, float& x, float& y) {
    asm("mov.b64 {%0, %1}, %2;" : "=f"(x), "=f"(y) : "l"(v));
}
__device__ __forceinline__ unsigned long long fmaf2(unsigned long long a,
                                                    unsigned long long b,
                                                    unsigned long long c) {
    unsigned long long d;
    asm("fma.rn.f32x2 %0, %1, %2, %3;" : "=l"(d) : "l"(a), "l"(b), "l"(c));
    return d;
}
__device__ __forceinline__ unsigned long long h2f2(__half2 h) {
    float2 f = __half22float2(h);
    return pkf2(f.x, f.y);
}

struct FragSet {
    uint32_t a[4][4];
    uint32_t b[2][4];
};

// ---------------------------------------------------------------- fp16 GEMM (R14 verbatim)
template <bool BIAS, typename OutT>
__global__ void __launch_bounds__(256, 2)
gemm_f16(const __half* __restrict__ A, const __half* __restrict__ Bt,
         const float* __restrict__ bias, OutT* __restrict__ C, int Ncols)
{
    extern __shared__ char smem[];
    const int tid  = threadIdx.x;
    const int wid  = tid >> 5, lane = tid & 31;
    const int g    = lane >> 2, tig = lane & 3;
    const int wm   = (wid >> 2) * 64;
    const int wn   = (wid & 3) * 32;
    const int bm   = blockIdx.y * BM;
    const int bn   = blockIdx.x * BN;
    const uint32_t sbase = smem_u32(smem);

    const int lm = lane >> 3, lr = lane & 7;
    const uint32_t aLane = (uint32_t)(((lm & 1) * 8 + lr) * ROWB + (lm >> 1) * 16);
    const uint32_t bLane = (uint32_t)(((lm >> 1) * 8 + lr) * ROWB + (lm & 1) * 16);
    const uint32_t aBase = (uint32_t)(wm * ROWB) + aLane;
    const uint32_t bBase = (uint32_t)(TILE_BYTES + wn * ROWB) + bLane;

    float c[4][4][4];
#pragma unroll
    for (int i = 0; i < 4; i++)
#pragma unroll
        for (int j = 0; j < 4; j++)
#pragma unroll
            for (int q = 0; q < 4; q++) c[i][j][q] = 0.f;

    auto load_tile = [&](int t, int s) {
        uint32_t st = sbase + (uint32_t)(s * STAGE_BYTES);
        const __half* Ab = A + (size_t)bm * DIM + t * BK;
#pragma unroll
        for (int i = 0; i < 2; i++) {
            int id = tid + i * 256;
            int r = id >> 2, ck = id & 3;
            cp16(st + (uint32_t)(r * ROWB + ck * 16),
                 Ab + (size_t)r * DIM + ck * 8);
        }
        uint32_t stB = st + TILE_BYTES;
        const __half* Bb = Bt + (size_t)bn * DIM + t * BK;
#pragma unroll
        for (int i = 0; i < 2; i++) {
            int id = tid + i * 256;
            int r = id >> 2, ck = id & 3;
            cp16(stB + (uint32_t)(r * ROWB + ck * 16),
                 Bb + (size_t)r * DIM + ck * 8);
        }
    };

    auto ld_frags = [&](FragSet& f, uint32_t stage, uint32_t ko) {
#pragma unroll
        for (int mt = 0; mt < 4; mt++)
            ldmx4(f.a[mt], stage + aBase + (uint32_t)(mt * 16 * ROWB) + ko);
#pragma unroll
        for (int p = 0; p < 2; p++)
            ldmx4(f.b[p], stage + bBase + (uint32_t)(p * 16 * ROWB) + ko);
    };

    auto mma_set = [&](const FragSet& f) {
#pragma unroll
        for (int mt = 0; mt < 4; mt++)
#pragma unroll
            for (int nt = 0; nt < 4; nt++) {
                const uint32_t* bb = &f.b[nt >> 1][(nt & 1) * 2];
                mma_f16(c[mt][nt], f.a[mt][0], f.a[mt][1], f.a[mt][2],
                        f.a[mt][3], bb[0], bb[1]);
            }
    };

    load_tile(0, 0); cp_commit();
    load_tile(1, 1); cp_commit();
    load_tile(2, 2); cp_commit();

    FragSet F, G;
    cp_wait<2>();
    __syncthreads();
    ld_frags(F, sbase, 0);

    for (int t = 0; t < TK; t++) {
        cp_wait<1>();
        __syncthreads();
        if (t + 3 < TK) load_tile(t + 3, (t + 3) % STAGES);
        cp_commit();

        const uint32_t scur = sbase + (uint32_t)((t % STAGES) * STAGE_BYTES);
        const uint32_t snxt = sbase + (uint32_t)(((t + 1) % STAGES) * STAGE_BYTES);

        ld_frags(G, scur, 32);
        mma_set(F);
        ld_frags(F, (t + 1 < TK) ? snxt : scur, 0);
        mma_set(G);
    }

#pragma unroll
    for (int mt = 0; mt < 4; mt++) {
#pragma unroll
        for (int nt = 0; nt < 4; nt++) {
            int col = bn + wn + nt * 8 + 2 * tig;
            float b0 = 0.f, b1 = 0.f;
            if (BIAS) { b0 = bias[col]; b1 = bias[col + 1]; }
            int r0 = bm + wm + mt * 16 + g;
            if (sizeof(OutT) == 2) {
                __half* Ch = reinterpret_cast<__half*>(C);
                uint32_t w0 = packh2(c[mt][nt][0] + b0, c[mt][nt][1] + b1);
                uint32_t w1 = packh2(c[mt][nt][2] + b0, c[mt][nt][3] + b1);
                *reinterpret_cast<uint32_t*>(Ch + (size_t)r0 * Ncols + col) = w0;
                *reinterpret_cast<uint32_t*>(Ch + (size_t)(r0 + 8) * Ncols + col) = w1;
            } else {
                float* Cf = reinterpret_cast<float*>(C);
                float2 v0 = make_float2(c[mt][nt][0] + b0, c[mt][nt][1] + b1);
                float2 v1 = make_float2(c[mt][nt][2] + b0, c[mt][nt][3] + b1);
                *reinterpret_cast<float2*>(Cf + (size_t)r0 * Ncols + col) = v0;
                *reinterpret_cast<float2*>(Cf + (size_t)(r0 + 8) * Ncols + col) = v1;
            }
        }
    }
}

// ---------------------------------------------------------------- fp32 -> fp16
__global__ void __launch_bounds__(256)
tohalf_kernel(const float* __restrict__ in, __half* __restrict__ out, size_t n4)
{
    size_t i = (size_t)blockIdx.x * blockDim.x + threadIdx.x;
    if (i >= n4) return;
    float4 v = reinterpret_cast<const float4*>(in)[i];
    uint2 o;
    o.x = packh2(v.x, v.y);
    o.y = packh2(v.z, v.w);
    reinterpret_cast<uint2*>(out)[i] = o;
}

// ---------------------------------------------------------------- transpose (+fp16)
__global__ void __launch_bounds__(256)
transpose_kernel(const float* __restrict__ in, __half* __restrict__ out,
                 int R, int Ccols)
{
    __shared__ float tile[32][33];
    int c0 = blockIdx.x * 32, r0 = blockIdx.y * 32;
    int tx = threadIdx.x & 31, ty = threadIdx.x >> 5;
    for (int i = ty; i < 32; i += 8)
        tile[i][tx] = in[(size_t)(r0 + i) * Ccols + c0 + tx];
    __syncthreads();
    for (int i = ty; i < 32; i += 8)
        out[(size_t)(c0 + i) * R + r0 + tx] = __float2half_rn(tile[tx][i]);
}

// ---------------------------------------------------------------- attention v2
// fp16 smem q/k/v; dots: thread = (h, i, j-pair) with shared q; packed f32x2
// accumulation in dots and PV.
__global__ void __launch_bounds__(256)
attn_kernel(const __half* __restrict__ qkv, const float* __restrict__ mask,
            __half* __restrict__ out)
{
    extern __shared__ char shraw[];
    __half* sq = reinterpret_cast<__half*>(shraw);
    __half* sk = sq + 8 * QPH;
    __half* sv = sq + 16 * QPH;
    float*  sd = reinterpret_cast<float*>(sq + 24 * QPH);   // [8][8][8]

    const int p   = blockIdx.x;
    const int tid = threadIdx.x;
    const __half* base = qkv + (size_t)p * N_TOK * INNER3;

    for (int s = tid; s < 1536; s += 256) {
        int row = s / 192;
        int c8  = s % 192;
        uint4 raw = *reinterpret_cast<const uint4*>(base + (size_t)row * INNER3 + c8 * 8);
        int col = c8 * 8;
        __half* dst; int cc;
        if (col < 512)       { dst = sq + row * QPH; cc = col; }
        else if (col < 1024) { dst = sk + row * QPH; cc = col - 512; }
        else                 { dst = sv + row * QPH; cc = col - 1024; }
        *reinterpret_cast<uint4*>(dst + cc) = raw;
    }
    __syncthreads();

    // dots: 256 threads, each computes 2 dots (j0, j0+1) sharing one q row
    {
        const int h  = tid >> 5;
        const int i  = (tid >> 2) & 7;
        const int j0 = (tid & 3) * 2;
        const uint4* qp  = reinterpret_cast<const uint4*>(sq + i * QPH + h * 64);
        const uint4* k0p = reinterpret_cast<const uint4*>(sk + j0 * QPH + h * 64);
        const uint4* k1p = reinterpret_cast<const uint4*>(sk + (j0 + 1) * QPH + h * 64);
        unsigned long long acc0 = 0ull, acc1 = 0ull;   // packed (0.0f, 0.0f)
#pragma unroll
        for (int d = 0; d < 8; d++) {
            uint4 qa = qp[d], ka = k0p[d], kb = k1p[d];
            const __half2* qh = reinterpret_cast<const __half2*>(&qa);
            const __half2* k0 = reinterpret_cast<const __half2*>(&ka);
            const __half2* k1 = reinterpret_cast<const __half2*>(&kb);
#pragma unroll
            for (int e = 0; e < 4; e++) {
                unsigned long long qf = h2f2(qh[e]);
                acc0 = fmaf2(qf, h2f2(k0[e]), acc0);
                acc1 = fmaf2(qf, h2f2(k1[e]), acc1);
            }
        }
        float a0x, a0y, a1x, a1y;
        upkf2(acc0, a0x, a0y);
        upkf2(acc1, a1x, a1y);
        float m0 = mask[(size_t)p * 64 + i * 8 + j0];
        float m1 = mask[(size_t)p * 64 + i * 8 + j0 + 1];
        sd[(h * 8 + i) * 8 + j0]     = (a0x + a0y) * SCALE_F * m0;
        sd[(h * 8 + i) * 8 + j0 + 1] = (a1x + a1y) * SCALE_F * m1;
    }
    __syncthreads();

    if (tid < 64) {
        int h = tid >> 3, i = tid & 7;
        float* row = &sd[(h * 8 + i) * 8];
        float mx = row[0];
#pragma unroll
        for (int j = 1; j < 8; j++) mx = fmaxf(mx, row[j]);
        float e[8], sum = 0.f;
#pragma unroll
        for (int j = 0; j < 8; j++) { e[j] = __expf(row[j] - mx); sum += e[j]; }
        float inv = 1.f / sum;
#pragma unroll
        for (int j = 0; j < 8; j++) row[j] = e[j] * inv;
    }
    __syncthreads();

    // PV with packed f32x2 accumulation
    __half* ob = out + (size_t)p * N_TOK * INNER;
    for (int s = tid; s < 1024; s += 256) {
        int i   = s >> 7;
        int c4  = s & 127;
        int col = c4 * 4;
        int h   = col >> 6;
        unsigned long long acc01 = 0ull, acc23 = 0ull;
#pragma unroll
        for (int j = 0; j < 8; j++) {
            float a = sd[(h * 8 + i) * 8 + j];
            unsigned long long a2 = pkf2(a, a);
            uint2 vv = *reinterpret_cast<const uint2*>(sv + j * QPH + col);
            const __half2* vh = reinterpret_cast<const __half2*>(&vv);
            acc01 = fmaf2(a2, h2f2(vh[0]), acc01);
            acc23 = fmaf2(a2, h2f2(vh[1]), acc23);
        }
        float x0, y0, x1, y1;
        upkf2(acc01, x0, y0);
        upkf2(acc23, x1, y1);
        uint2 o;
        o.x = packh2(x0, y0);
        o.y = packh2(x1, y1);
        *reinterpret_cast<uint2*>(ob + (size_t)i * INNER + col) = o;
    }
}

// ---------------------------------------------------------------- launch
extern "C" void kernel_launch(void* const* d_in, const int* in_sizes, int n_in,
                              void* d_out, int out_size)
{
    (void)in_sizes; (void)n_in; (void)out_size;
    const float* x     = (const float*)d_in[0];
    const float* mask  = (const float*)d_in[1];
    const float* w_qkv = (const float*)d_in[2];
    const float* w_out = (const float*)d_in[3];
    const float* b_out = (const float*)d_in[4];
    float* out = (float*)d_out;

    __half *qkv_p, *att_p, *xtf_p, *wqkvT_p, *woutT_p;
    cudaGetSymbolAddress((void**)&qkv_p, g_qkv);
    cudaGetSymbolAddress((void**)&att_p, g_att);
    cudaGetSymbolAddress((void**)&xtf_p, g_xtf);
    cudaGetSymbolAddress((void**)&wqkvT_p, g_wqkvT);
    cudaGetSymbolAddress((void**)&woutT_p, g_woutT);

    cudaFuncSetAttribute((const void*)gemm_f16<false, __half>,
                         cudaFuncAttributeMaxDynamicSharedMemorySize, GEMM_SMEM);
    cudaFuncSetAttribute((const void*)gemm_f16<true, float>,
                         cudaFuncAttributeMaxDynamicSharedMemorySize, GEMM_SMEM);
    const int ATTN_SMEM = 24 * QPH * 2 + 512 * 4;   // 27008 B
    cudaFuncSetAttribute((const void*)attn_kernel,
                         cudaFuncAttributeMaxDynamicSharedMemorySize, ATTN_SMEM);

    const size_t n4 = (size_t)M_ROWS * DIM / 4;
    tohalf_kernel<<<(unsigned)((n4 + 255) / 256), 256>>>(x, xtf_p, n4);
    transpose_kernel<<<dim3(INNER3 / 32, DIM / 32), 256>>>(w_qkv, wqkvT_p, DIM, INNER3);
    transpose_kernel<<<dim3(INNER  / 32, DIM / 32), 256>>>(w_out, woutT_p, DIM, INNER);

    gemm_f16<false, __half><<<dim3(INNER3 / BN, M_ROWS / BM), 256, GEMM_SMEM>>>(
        xtf_p, wqkvT_p, nullptr, qkv_p, INNER3);
    attn_kernel<<<N_PIX, 256, ATTN_SMEM>>>(qkv_p, mask, att_p);
    gemm_f16<true, float><<<dim3(INNER / BN, M_ROWS / BM), 256, GEMM_SMEM>>>(
        att_p, woutT_p, b_out, out, INNER);
}

// round 16
// speedup vs baseline: 1.0446x; 1.0446x over previous
#include <cuda_runtime.h>
#include <cuda_fp16.h>
#include <cstdint>
#include <math.h>

// ---------------------------------------------------------------- constants
#define N_PIX     8192
#define N_TOK     8
#define DIM       512
#define INNER     512
#define INNER3    1536
#define SCALE_F   0.125f
#define M_ROWS    65536

// GEMM tiling (fp16 m16n8k16): CTA 128x128, 128 threads, 4 warps 2x2,
// warp tile 64x64, FragSet cross-tile pipeline, 2 CTAs/SM.
#define TPB    128
#define BM     128
#define BN     128
#define BK     32
#define STAGES 4
#define TK     (DIM / BK)               // 16 K-tiles
#define ROWB   80
#define TILE_BYTES  (128 * ROWB)        // 10240
#define STAGE_BYTES (2 * TILE_BYTES)    // 20480
#define GEMM_SMEM   (STAGES * STAGE_BYTES)  // 81920

#define QPH    520                      // attn smem pitch in halves

// Scratch (__device__ globals per allocation rules)
__device__ __half g_qkv[(size_t)M_ROWS * INNER3];
__device__ __half g_att[(size_t)M_ROWS * INNER];
__device__ __half g_xtf[(size_t)M_ROWS * DIM];
__device__ __half g_wqkvT[(size_t)INNER3 * DIM];
__device__ __half g_woutT[(size_t)INNER * DIM];

// ---------------------------------------------------------------- helpers
__device__ __forceinline__ uint32_t smem_u32(const void* p) {
    uint32_t a;
    asm("{ .reg .u64 t; cvta.to.shared.u64 t, %1; cvt.u32.u64 %0, t; }"
        : "=r"(a) : "l"(p));
    return a;
}
__device__ __forceinline__ void cp16(uint32_t dst, const void* src) {
    asm volatile("cp.async.cg.shared.global [%0], [%1], 16;"
                 :: "r"(dst), "l"(src));
}
__device__ __forceinline__ void cp_commit() {
    asm volatile("cp.async.commit_group;" ::: "memory");
}
template <int N> __device__ __forceinline__ void cp_wait() {
    asm volatile("cp.async.wait_group %0;" :: "n"(N) : "memory");
}
__device__ __forceinline__ void ldmx4(uint32_t* r, uint32_t addr) {
    asm volatile("ldmatrix.sync.aligned.m8n8.x4.shared.b16 {%0,%1,%2,%3}, [%4];"
                 : "=r"(r[0]), "=r"(r[1]), "=r"(r[2]), "=r"(r[3]) : "r"(addr));
}
__device__ __forceinline__ void mma_f16(float* c, uint32_t a0, uint32_t a1,
                                        uint32_t a2, uint32_t a3,
                                        uint32_t b0, uint32_t b1) {
    asm volatile(
        "mma.sync.aligned.m16n8k16.row.col.f32.f16.f16.f32 "
        "{%0,%1,%2,%3}, {%4,%5,%6,%7}, {%8,%9}, {%0,%1,%2,%3};"
        : "+f"(c[0]), "+f"(c[1]), "+f"(c[2]), "+f"(c[3])
        : "r"(a0), "r"(a1), "r"(a2), "r"(a3), "r"(b0), "r"(b1));
}
__device__ __forceinline__ uint32_t packh2(float x, float y) {
    __half2 h = __floats2half2_rn(x, y);
    return *reinterpret_cast<uint32_t*>(&h);
}

struct FragSet {
    uint32_t a[4][4];
    uint32_t b[4][4];
};

// ---------------------------------------------------------------- fp16 GEMM
// C[M, Ncols] = A[M,512] @ Bt[Ncols,512]^T (+bias)
template <bool BIAS, typename OutT>
__global__ void __launch_bounds__(TPB, 2)
gemm_f16(const __half* __restrict__ A, const __half* __restrict__ Bt,
         const float* __restrict__ bias, OutT* __restrict__ C, int Ncols)
{
    extern __shared__ char smem[];
    const int tid  = threadIdx.x;
    const int wid  = tid >> 5, lane = tid & 31;
    const int g    = lane >> 2, tig = lane & 3;
    const int wm   = (wid >> 1) * 64;       // 2 m-groups
    const int wn   = (wid & 1) * 64;        // 2 n-groups
    const int bm   = blockIdx.y * BM;
    const int bn   = blockIdx.x * BN;
    const uint32_t sbase = smem_u32(smem);

    const int lm = lane >> 3, lr = lane & 7;
    const uint32_t aLane = (uint32_t)(((lm & 1) * 8 + lr) * ROWB + (lm >> 1) * 16);
    const uint32_t bLane = (uint32_t)(((lm >> 1) * 8 + lr) * ROWB + (lm & 1) * 16);
    const uint32_t aBase = (uint32_t)(wm * ROWB) + aLane;
    const uint32_t bBase = (uint32_t)(TILE_BYTES + wn * ROWB) + bLane;

    float c[4][8][4];
#pragma unroll
    for (int i = 0; i < 4; i++)
#pragma unroll
        for (int j = 0; j < 8; j++)
#pragma unroll
            for (int q = 0; q < 4; q++) c[i][j][q] = 0.f;

    auto load_tile = [&](int t, int s) {
        uint32_t st = sbase + (uint32_t)(s * STAGE_BYTES);
        const __half* Ab = A + (size_t)bm * DIM + t * BK;
#pragma unroll
        for (int i = 0; i < 4; i++) {          // A: 512 16B chunks / 128 thr
            int id = tid + i * TPB;
            int r = id >> 2, ck = id & 3;
            cp16(st + (uint32_t)(r * ROWB + ck * 16),
                 Ab + (size_t)r * DIM + ck * 8);
        }
        uint32_t stB = st + TILE_BYTES;
        const __half* Bb = Bt + (size_t)bn * DIM + t * BK;
#pragma unroll
        for (int i = 0; i < 4; i++) {
            int id = tid + i * TPB;
            int r = id >> 2, ck = id & 3;
            cp16(stB + (uint32_t)(r * ROWB + ck * 16),
                 Bb + (size_t)r * DIM + ck * 8);
        }
    };

    auto ld_frags = [&](FragSet& f, uint32_t stage, uint32_t ko) {
#pragma unroll
        for (int mt = 0; mt < 4; mt++)
            ldmx4(f.a[mt], stage + aBase + (uint32_t)(mt * 16 * ROWB) + ko);
#pragma unroll
        for (int p = 0; p < 4; p++)
            ldmx4(f.b[p], stage + bBase + (uint32_t)(p * 16 * ROWB) + ko);
    };

    auto mma_set = [&](const FragSet& f) {
#pragma unroll
        for (int mt = 0; mt < 4; mt++)
#pragma unroll
            for (int nt = 0; nt < 8; nt++) {
                const uint32_t* bb = &f.b[nt >> 1][(nt & 1) * 2];
                mma_f16(c[mt][nt], f.a[mt][0], f.a[mt][1], f.a[mt][2],
                        f.a[mt][3], bb[0], bb[1]);
            }
    };

    // prologue: 3 tiles in flight
    load_tile(0, 0); cp_commit();
    load_tile(1, 1); cp_commit();
    load_tile(2, 2); cp_commit();

    FragSet F, G;
    cp_wait<2>();                 // tile 0 resident
    __syncthreads();
    ld_frags(F, sbase, 0);        // chunk0 of tile 0

    for (int t = 0; t < TK; t++) {
        cp_wait<1>();             // tiles <= t+1 resident
        __syncthreads();          // all warps done with tile t-1 frag reads
        if (t + 3 < TK) load_tile(t + 3, (t + 3) % STAGES);
        cp_commit();

        const uint32_t scur = sbase + (uint32_t)((t % STAGES) * STAGE_BYTES);
        const uint32_t snxt = sbase + (uint32_t)(((t + 1) % STAGES) * STAGE_BYTES);

        ld_frags(G, scur, 32);                       // chunk1 of tile t
        mma_set(F);                                  // chunk0 of tile t
        ld_frags(F, (t + 1 < TK) ? snxt : scur, 0);  // chunk0 of tile t+1
        mma_set(G);                                  // chunk1 of tile t
    }

#pragma unroll
    for (int mt = 0; mt < 4; mt++) {
#pragma unroll
        for (int nt = 0; nt < 8; nt++) {
            int col = bn + wn + nt * 8 + 2 * tig;
            float b0 = 0.f, b1 = 0.f;
            if (BIAS) { b0 = bias[col]; b1 = bias[col + 1]; }
            int r0 = bm + wm + mt * 16 + g;
            if (sizeof(OutT) == 2) {
                __half* Ch = reinterpret_cast<__half*>(C);
                uint32_t w0 = packh2(c[mt][nt][0] + b0, c[mt][nt][1] + b1);
                uint32_t w1 = packh2(c[mt][nt][2] + b0, c[mt][nt][3] + b1);
                *reinterpret_cast<uint32_t*>(Ch + (size_t)r0 * Ncols + col) = w0;
                *reinterpret_cast<uint32_t*>(Ch + (size_t)(r0 + 8) * Ncols + col) = w1;
            } else {
                float* Cf = reinterpret_cast<float*>(C);
                float2 v0 = make_float2(c[mt][nt][0] + b0, c[mt][nt][1] + b1);
                float2 v1 = make_float2(c[mt][nt][2] + b0, c[mt][nt][3] + b1);
                *reinterpret_cast<float2*>(Cf + (size_t)r0 * Ncols + col) = v0;
                *reinterpret_cast<float2*>(Cf + (size_t)(r0 + 8) * Ncols + col) = v1;
            }
        }
    }
}

// ---------------------------------------------------------------- fp32 -> fp16
__global__ void __launch_bounds__(256)
tohalf_kernel(const float* __restrict__ in, __half* __restrict__ out, size_t n4)
{
    size_t i = (size_t)blockIdx.x * blockDim.x + threadIdx.x;
    if (i >= n4) return;
    float4 v = reinterpret_cast<const float4*>(in)[i];
    uint2 o;
    o.x = packh2(v.x, v.y);
    o.y = packh2(v.z, v.w);
    reinterpret_cast<uint2*>(out)[i] = o;
}

// ---------------------------------------------------------------- transpose (+fp16)
__global__ void __launch_bounds__(256)
transpose_kernel(const float* __restrict__ in, __half* __restrict__ out,
                 int R, int Ccols)
{
    __shared__ float tile[32][33];
    int c0 = blockIdx.x * 32, r0 = blockIdx.y * 32;
    int tx = threadIdx.x & 31, ty = threadIdx.x >> 5;
    for (int i = ty; i < 32; i += 8)
        tile[i][tx] = in[(size_t)(r0 + i) * Ccols + c0 + tx];
    __syncthreads();
    for (int i = ty; i < 32; i += 8)
        out[(size_t)(c0 + i) * R + r0 + tx] = __float2half_rn(tile[tx][i]);
}

// ---------------------------------------------------------------- attention (R14/R11 verbatim)
__global__ void __launch_bounds__(256)
attn_kernel(const __half* __restrict__ qkv, const float* __restrict__ mask,
            __half* __restrict__ out)
{
    extern __shared__ char shraw[];
    __half* sq = reinterpret_cast<__half*>(shraw);
    __half* sk = sq + 8 * QPH;
    __half* sv = sq + 16 * QPH;
    float*  sd = reinterpret_cast<float*>(sq + 24 * QPH);   // [8][8][8]

    const int p   = blockIdx.x;
    const int tid = threadIdx.x;
    const __half* base = qkv + (size_t)p * N_TOK * INNER3;

    for (int s = tid; s < 1536; s += 256) {
        int row = s / 192;
        int c8  = s % 192;
        uint4 raw = *reinterpret_cast<const uint4*>(base + (size_t)row * INNER3 + c8 * 8);
        int col = c8 * 8;
        __half* dst; int cc;
        if (col < 512)       { dst = sq + row * QPH; cc = col; }
        else if (col < 1024) { dst = sk + row * QPH; cc = col - 512; }
        else                 { dst = sv + row * QPH; cc = col - 1024; }
        *reinterpret_cast<uint4*>(dst + cc) = raw;
    }
    __syncthreads();

    for (int s = tid; s < 512; s += 256) {
        int h = s >> 6, i = (s >> 3) & 7, j = s & 7;
        const uint4* qp = reinterpret_cast<const uint4*>(sq + i * QPH + h * 64);
        const uint4* kp = reinterpret_cast<const uint4*>(sk + j * QPH + h * 64);
        float acc = 0.f;
#pragma unroll
        for (int d = 0; d < 8; d++) {
            uint4 qa = qp[d], kb = kp[d];
            const __half2* qh = reinterpret_cast<const __half2*>(&qa);
            const __half2* kh = reinterpret_cast<const __half2*>(&kb);
#pragma unroll
            for (int e = 0; e < 4; e++) {
                float2 qf = __half22float2(qh[e]);
                float2 kf = __half22float2(kh[e]);
                acc = fmaf(qf.x, kf.x, acc);
                acc = fmaf(qf.y, kf.y, acc);
            }
        }
        float m = mask[(size_t)p * 64 + i * 8 + j];
        sd[(h * 8 + i) * 8 + j] = acc * SCALE_F * m;
    }
    __syncthreads();

    if (tid < 64) {
        int h = tid >> 3, i = tid & 7;
        float* row = &sd[(h * 8 + i) * 8];
        float mx = row[0];
#pragma unroll
        for (int j = 1; j < 8; j++) mx = fmaxf(mx, row[j]);
        float e[8], sum = 0.f;
#pragma unroll
        for (int j = 0; j < 8; j++) { e[j] = __expf(row[j] - mx); sum += e[j]; }
        float inv = 1.f / sum;
#pragma unroll
        for (int j = 0; j < 8; j++) row[j] = e[j] * inv;
    }
    __syncthreads();

    __half* ob = out + (size_t)p * N_TOK * INNER;
    for (int s = tid; s < 1024; s += 256) {
        int i   = s >> 7;
        int c4  = s & 127;
        int col = c4 * 4;
        int h   = col >> 6;
        float4 acc = make_float4(0.f, 0.f, 0.f, 0.f);
#pragma unroll
        for (int j = 0; j < 8; j++) {
            float a = sd[(h * 8 + i) * 8 + j];
            uint2 vv = *reinterpret_cast<const uint2*>(sv + j * QPH + col);
            const __half2* vh = reinterpret_cast<const __half2*>(&vv);
            float2 v0 = __half22float2(vh[0]);
            float2 v1 = __half22float2(vh[1]);
            acc.x = fmaf(a, v0.x, acc.x);
            acc.y = fmaf(a, v0.y, acc.y);
            acc.z = fmaf(a, v1.x, acc.z);
            acc.w = fmaf(a, v1.y, acc.w);
        }
        uint2 o;
        o.x = packh2(acc.x, acc.y);
        o.y = packh2(acc.z, acc.w);
        *reinterpret_cast<uint2*>(ob + (size_t)i * INNER + col) = o;
    }
}

// ---------------------------------------------------------------- launch
extern "C" void kernel_launch(void* const* d_in, const int* in_sizes, int n_in,
                              void* d_out, int out_size)
{
    (void)in_sizes; (void)n_in; (void)out_size;
    const float* x     = (const float*)d_in[0];
    const float* mask  = (const float*)d_in[1];
    const float* w_qkv = (const float*)d_in[2];
    const float* w_out = (const float*)d_in[3];
    const float* b_out = (const float*)d_in[4];
    float* out = (float*)d_out;

    __half *qkv_p, *att_p, *xtf_p, *wqkvT_p, *woutT_p;
    cudaGetSymbolAddress((void**)&qkv_p, g_qkv);
    cudaGetSymbolAddress((void**)&att_p, g_att);
    cudaGetSymbolAddress((void**)&xtf_p, g_xtf);
    cudaGetSymbolAddress((void**)&wqkvT_p, g_wqkvT);
    cudaGetSymbolAddress((void**)&woutT_p, g_woutT);

    cudaFuncSetAttribute((const void*)gemm_f16<false, __half>,
                         cudaFuncAttributeMaxDynamicSharedMemorySize, GEMM_SMEM);
    cudaFuncSetAttribute((const void*)gemm_f16<true, float>,
                         cudaFuncAttributeMaxDynamicSharedMemorySize, GEMM_SMEM);
    const int ATTN_SMEM = 24 * QPH * 2 + 512 * 4;   // 27008 B
    cudaFuncSetAttribute((const void*)attn_kernel,
                         cudaFuncAttributeMaxDynamicSharedMemorySize, ATTN_SMEM);

    const size_t n4 = (size_t)M_ROWS * DIM / 4;
    tohalf_kernel<<<(unsigned)((n4 + 255) / 256), 256>>>(x, xtf_p, n4);
    transpose_kernel<<<dim3(INNER3 / 32, DIM / 32), 256>>>(w_qkv, wqkvT_p, DIM, INNER3);
    transpose_kernel<<<dim3(INNER  / 32, DIM / 32), 256>>>(w_out, woutT_p, DIM, INNER);

    // 1) qkv = x @ w_qkv  (fp16 in/out)
    gemm_f16<false, __half><<<dim3(INNER3 / BN, M_ROWS / BM), TPB, GEMM_SMEM>>>(
        xtf_p, wqkvT_p, nullptr, qkv_p, INNER3);
    // 2) attention (fp16 in/out, fp32 math)
    attn_kernel<<<N_PIX, 256, ATTN_SMEM>>>(qkv_p, mask, att_p);
    // 3) out = att @ w_out + b_out  (fp32 out)
    gemm_f16<true, float><<<dim3(INNER / BN, M_ROWS / BM), TPB, GEMM_SMEM>>>(
        att_p, woutT_p, b_out, out, INNER);
}